// round 11
// baseline (speedup 1.0000x reference)
#include <cuda_runtime.h>

// e3nn uvu tensor product, HBM-bound streaming kernel.
//   x: (B, 1024) = 256x0e + 256x1o (u-major triplets)
//   y: (B, 4), w: (1280,), out: (B, 1024)
//
// out0[u]   = C0*w0[u]*x0[u]*y0 + C0*C1*w1[u]*dot(x1[u], y1)
// out1[u,k] = C1*w2[u]*x0[u]*y1[k] + C1*w3[u]*y0*x1[u,k] + C2*w4[u]*cross(x1[u],y1)[k]
//
// R10: quantum-sweep endpoint. ZPB=4: one row-group per CTA (grid 32768),
// straight-line body, minimal CTA-duration spread.
// Sweep history: ZPB 64/32/16/8 -> 171.8/163.5/159.8/157.7 us.

#define ZPB 4           // batch rows per block (16KB footprint, 1 iteration)
#define THREADS 256     // 4 row-slices x 64 u-groups

__global__ __launch_bounds__(THREADS)
void tp_uvu_kernel(const float* __restrict__ x,
                   const float* __restrict__ y,
                   const float* __restrict__ w,
                   float* __restrict__ out,
                   int B)
{
    const int tid = threadIdx.x;
    const int ug  = tid & 63;        // u-group: 4 consecutive u's
    const int zl  = tid >> 6;        // 0..3 row slice within block
    const int u   = ug << 2;

    const int z = blockIdx.x * ZPB + zl;
    if (z >= B) return;

    const float C0  = 0.70710678118654752f;   // 1/sqrt(2)
    const float C1  = 0.57735026918962576f;   // 1/sqrt(3)
    const float C01 = C0 * C1;
    const float C2  = 0.40824829046386302f;   // 1/sqrt(6)

    const float* xr   = x   + (size_t)z * 1024;
    float*       orow = out + (size_t)z * 1024;

    // Front-batch ALL independent global loads (x row, y row, weights).
    const float4 yv  = *(const float4*)(y + (size_t)z * 4);
    const float4 x0v = *(const float4*)(xr + u);
    const float4 xa  = *(const float4*)(xr + 256 + u * 3);
    const float4 xb  = *(const float4*)(xr + 256 + u * 3 + 4);
    const float4 xc  = *(const float4*)(xr + 256 + u * 3 + 8);

    const float4 w0 = *(const float4*)(w + 0 * 256 + u);
    const float4 w1 = *(const float4*)(w + 1 * 256 + u);
    const float4 w2 = *(const float4*)(w + 2 * 256 + u);
    const float4 w3 = *(const float4*)(w + 3 * 256 + u);
    const float4 w4 = *(const float4*)(w + 4 * 256 + u);

    const float a0[4] = {C0 * w0.x, C0 * w0.y, C0 * w0.z, C0 * w0.w};
    const float a1[4] = {C01 * w1.x, C01 * w1.y, C01 * w1.z, C01 * w1.w};
    const float a2[4] = {C1 * w2.x, C1 * w2.y, C1 * w2.z, C1 * w2.w};
    const float a3[4] = {C1 * w3.x, C1 * w3.y, C1 * w3.z, C1 * w3.w};
    const float a4[4] = {C2 * w4.x, C2 * w4.y, C2 * w4.z, C2 * w4.w};

    const float y0 = yv.x, e1x = yv.y, e1y = yv.z, e1z = yv.w;

    // unpack x1 vectors for the 4 u's
    const float vx[4]  = {xa.x, xa.w, xb.z, xc.y};
    const float vy[4]  = {xa.y, xb.x, xb.w, xc.z};
    const float vz[4]  = {xa.z, xb.y, xc.x, xc.w};
    const float x0s[4] = {x0v.x, x0v.y, x0v.z, x0v.w};

    float o0[4], ox[4], oy[4], oz[4];
    #pragma unroll
    for (int j = 0; j < 4; ++j) {
        const float dot = vx[j] * e1x + vy[j] * e1y + vz[j] * e1z;
        o0[j] = a0[j] * x0s[j] * y0 + a1[j] * dot;

        const float cx = vy[j] * e1z - vz[j] * e1y;
        const float cy = vz[j] * e1x - vx[j] * e1z;
        const float cz = vx[j] * e1y - vy[j] * e1x;

        const float s2 = a2[j] * x0s[j];   // scales y1
        const float s3 = a3[j] * y0;       // scales x1

        ox[j] = s2 * e1x + s3 * vx[j] + a4[j] * cx;
        oy[j] = s2 * e1y + s3 * vy[j] + a4[j] * cy;
        oz[j] = s2 * e1z + s3 * vz[j] + a4[j] * cz;
    }

    // stores: same layout as input
    *(float4*)(orow + u) = make_float4(o0[0], o0[1], o0[2], o0[3]);
    *(float4*)(orow + 256 + u * 3)     = make_float4(ox[0], oy[0], oz[0], ox[1]);
    *(float4*)(orow + 256 + u * 3 + 4) = make_float4(oy[1], oz[1], ox[2], oy[2]);
    *(float4*)(orow + 256 + u * 3 + 8) = make_float4(oz[2], ox[3], oy[3], oz[3]);
}

extern "C" void kernel_launch(void* const* d_in, const int* in_sizes, int n_in,
                              void* d_out, int out_size)
{
    const float* x = (const float*)d_in[0];
    const float* y = (const float*)d_in[1];
    const float* w = (const float*)d_in[2];
    float* out = (float*)d_out;

    const int B = in_sizes[0] / 1024;
    const int grid = (B + ZPB - 1) / ZPB;
    tp_uvu_kernel<<<grid, THREADS>>>(x, y, w, out, B);
}

// round 13
// speedup vs baseline: 1.0133x; 1.0133x over previous
#include <cuda_runtime.h>

// e3nn uvu tensor product, HBM-bound streaming kernel.
//   x: (B, 1024) = 256x0e + 256x1o (u-major triplets)
//   y: (B, 4), w: (1280,), out: (B, 1024)
//
// out0[u]   = C0*w0[u]*x0[u]*y0 + C0*C1*w1[u]*dot(x1[u], y1)
// out1[u,k] = C1*w2[u]*x0[u]*y1[k] + C1*w3[u]*y0*x1[u,k] + C2*w4[u]*cross(x1[u],y1)[k]
//
// R11: ZPB=8 (optimal quantum from sweep) with BATCHED read/write runs:
// both row-groups' 10 LDG.128 issued first, all 8 STG.128 issued last,
// to halve per-warp DRAM read/write turnaround frequency.

#define ZPB 8           // batch rows per block, processed as ONE batched body
#define THREADS 256     // 4 row-slices x 64 u-groups

__global__ __launch_bounds__(THREADS)
void tp_uvu_kernel(const float* __restrict__ x,
                   const float* __restrict__ y,
                   const float* __restrict__ w,
                   float* __restrict__ out,
                   int B)
{
    const int tid = threadIdx.x;
    const int ug  = tid & 63;        // u-group: 4 consecutive u's
    const int zl  = tid >> 6;        // 0..3 row slice within block
    const int u   = ug << 2;

    const float C0  = 0.70710678118654752f;   // 1/sqrt(2)
    const float C1  = 0.57735026918962576f;   // 1/sqrt(3)
    const float C01 = C0 * C1;
    const float C2  = 0.40824829046386302f;   // 1/sqrt(6)

    const float4 w0 = *(const float4*)(w + 0 * 256 + u);
    const float4 w1 = *(const float4*)(w + 1 * 256 + u);
    const float4 w2 = *(const float4*)(w + 2 * 256 + u);
    const float4 w3 = *(const float4*)(w + 3 * 256 + u);
    const float4 w4 = *(const float4*)(w + 4 * 256 + u);

    const float a0[4] = {C0 * w0.x, C0 * w0.y, C0 * w0.z, C0 * w0.w};
    const float a1[4] = {C01 * w1.x, C01 * w1.y, C01 * w1.z, C01 * w1.w};
    const float a2[4] = {C1 * w2.x, C1 * w2.y, C1 * w2.z, C1 * w2.w};
    const float a3[4] = {C1 * w3.x, C1 * w3.y, C1 * w3.z, C1 * w3.w};
    const float a4[4] = {C2 * w4.x, C2 * w4.y, C2 * w4.z, C2 * w4.w};

    const int z0 = blockIdx.x * ZPB + zl;   // row-group 0 row
    const int z1 = z0 + 4;                  // row-group 1 row
    if (z0 >= B) return;
    const bool has1 = (z1 < B);             // always true for B % 8 == 0

    // ── READ RUN: all loads for both row-groups, issued back-to-back ──
    const float* xr0 = x + (size_t)z0 * 1024;
    const float4 yv0  = *(const float4*)(y + (size_t)z0 * 4);
    const float4 x0v0 = *(const float4*)(xr0 + u);
    const float4 xa0  = *(const float4*)(xr0 + 256 + u * 3);
    const float4 xb0  = *(const float4*)(xr0 + 256 + u * 3 + 4);
    const float4 xc0  = *(const float4*)(xr0 + 256 + u * 3 + 8);

    float4 yv1, x0v1, xa1, xb1, xc1;
    if (has1) {
        const float* xr1 = x + (size_t)z1 * 1024;
        yv1  = *(const float4*)(y + (size_t)z1 * 4);
        x0v1 = *(const float4*)(xr1 + u);
        xa1  = *(const float4*)(xr1 + 256 + u * 3);
        xb1  = *(const float4*)(xr1 + 256 + u * 3 + 4);
        xc1  = *(const float4*)(xr1 + 256 + u * 3 + 8);
    }

    // ── COMPUTE both row-groups ──
    float4 r0a, r0b, r0c, r0d;   // group 0 outputs
    float4 r1a, r1b, r1c, r1d;   // group 1 outputs

    #pragma unroll
    for (int grp = 0; grp < 2; ++grp) {
        if (grp == 1 && !has1) break;
        const float4 yv  = grp ? yv1  : yv0;
        const float4 x0v = grp ? x0v1 : x0v0;
        const float4 xa  = grp ? xa1  : xa0;
        const float4 xb  = grp ? xb1  : xb0;
        const float4 xc  = grp ? xc1  : xc0;

        const float y0 = yv.x, e1x = yv.y, e1y = yv.z, e1z = yv.w;
        const float vx[4]  = {xa.x, xa.w, xb.z, xc.y};
        const float vy[4]  = {xa.y, xb.x, xb.w, xc.z};
        const float vz[4]  = {xa.z, xb.y, xc.x, xc.w};
        const float x0s[4] = {x0v.x, x0v.y, x0v.z, x0v.w};

        float o0[4], ox[4], oy[4], oz[4];
        #pragma unroll
        for (int j = 0; j < 4; ++j) {
            const float dot = vx[j] * e1x + vy[j] * e1y + vz[j] * e1z;
            o0[j] = a0[j] * x0s[j] * y0 + a1[j] * dot;

            const float cx = vy[j] * e1z - vz[j] * e1y;
            const float cy = vz[j] * e1x - vx[j] * e1z;
            const float cz = vx[j] * e1y - vy[j] * e1x;

            const float s2 = a2[j] * x0s[j];
            const float s3 = a3[j] * y0;

            ox[j] = s2 * e1x + s3 * vx[j] + a4[j] * cx;
            oy[j] = s2 * e1y + s3 * vy[j] + a4[j] * cy;
            oz[j] = s2 * e1z + s3 * vz[j] + a4[j] * cz;
        }

        const float4 pa = make_float4(o0[0], o0[1], o0[2], o0[3]);
        const float4 pb = make_float4(ox[0], oy[0], oz[0], ox[1]);
        const float4 pc = make_float4(oy[1], oz[1], ox[2], oy[2]);
        const float4 pd = make_float4(oz[2], ox[3], oy[3], oz[3]);
        if (grp == 0) { r0a = pa; r0b = pb; r0c = pc; r0d = pd; }
        else          { r1a = pa; r1b = pb; r1c = pc; r1d = pd; }
    }

    // ── WRITE RUN: all stores for both row-groups, issued back-to-back ──
    float* o0row = out + (size_t)z0 * 1024;
    *(float4*)(o0row + u)               = r0a;
    *(float4*)(o0row + 256 + u * 3)     = r0b;
    *(float4*)(o0row + 256 + u * 3 + 4) = r0c;
    *(float4*)(o0row + 256 + u * 3 + 8) = r0d;
    if (has1) {
        float* o1row = out + (size_t)z1 * 1024;
        *(float4*)(o1row + u)               = r1a;
        *(float4*)(o1row + 256 + u * 3)     = r1b;
        *(float4*)(o1row + 256 + u * 3 + 4) = r1c;
        *(float4*)(o1row + 256 + u * 3 + 8) = r1d;
    }
}

extern "C" void kernel_launch(void* const* d_in, const int* in_sizes, int n_in,
                              void* d_out, int out_size)
{
    const float* x = (const float*)d_in[0];
    const float* y = (const float*)d_in[1];
    const float* w = (const float*)d_in[2];
    float* out = (float*)d_out;

    const int B = in_sizes[0] / 1024;
    const int grid = (B + ZPB - 1) / ZPB;
    tp_uvu_kernel<<<grid, THREADS>>>(x, y, w, out, B);
}